// round 2
// baseline (speedup 1.0000x reference)
#include <cuda_runtime.h>

// LIF neuron, T=4 unrolled, 2 neurons per thread.
// Layout [B, N, T], T innermost -> one float4 per neuron.
// Both input pairs loaded up-front (MLP=4 LDG.128) with streaming hints;
// stores also streaming (zero reuse workload).

#define TAU 0.25f

__device__ __forceinline__ float4 lif4(float4 xv, float4 lv, float thre)
{
    float4 ov;
    // t = 0: u0 = 0 -> decay term is 0
    float u = xv.x + lv.x;
    float o = (u > thre) ? u : 0.0f;
    ov.x = o;
    // t = 1
    float reset = (o > thre) ? 0.0f : 1.0f;
    u = TAU * u * reset + xv.y + lv.y;
    o = (u > thre) ? u : 0.0f;
    ov.y = o;
    // t = 2
    reset = (o > thre) ? 0.0f : 1.0f;
    u = TAU * u * reset + xv.z + lv.z;
    o = (u > thre) ? u : 0.0f;
    ov.z = o;
    // t = 3
    reset = (o > thre) ? 0.0f : 1.0f;
    u = TAU * u * reset + xv.w + lv.w;
    o = (u > thre) ? u : 0.0f;
    ov.w = o;
    return ov;
}

__global__ __launch_bounds__(256) void lif_kernel2(
    const float4* __restrict__ x,
    const float4* __restrict__ lat,
    const float* __restrict__ w,
    float4* __restrict__ out,
    int n)   // n = B*N neurons (float4 elements)
{
    // Each block covers 2*blockDim consecutive float4s; thread t handles
    // base+t and base+t+blockDim -> every LDG.128 is a contiguous 512B
    // warp segment.
    int base = blockIdx.x * (blockDim.x * 2) + threadIdx.x;
    int i0 = base;
    int i1 = base + blockDim.x;

    const float thre = tanhf(w[0]);

    bool p0 = i0 < n;
    bool p1 = i1 < n;

    // Front-batch all 4 loads (streaming: read-once data, evict-first)
    float4 x0, l0, x1, l1;
    if (p0) { x0 = __ldcs(&x[i0]); l0 = __ldcs(&lat[i0]); }
    if (p1) { x1 = __ldcs(&x[i1]); l1 = __ldcs(&lat[i1]); }

    if (p0) { float4 o0 = lif4(x0, l0, thre); __stcs(&out[i0], o0); }
    if (p1) { float4 o1 = lif4(x1, l1, thre); __stcs(&out[i1], o1); }
}

extern "C" void kernel_launch(void* const* d_in, const int* in_sizes, int n_in,
                              void* d_out, int out_size)
{
    const float4* x   = (const float4*)d_in[0];  // [B, N, T] float32
    const float4* lat = (const float4*)d_in[1];  // [B, N, T] float32
    const float*  w   = (const float*)d_in[2];   // scalar
    float4* out = (float4*)d_out;

    int n = in_sizes[0] / 4;            // neurons (B*N)
    int block = 256;
    int per_block = block * 2;          // 2 neurons per thread
    int grid = (n + per_block - 1) / per_block;
    lif_kernel2<<<grid, block>>>(x, lat, w, out, n);
}